// round 2
// baseline (speedup 1.0000x reference)
#include <cuda_runtime.h>

#define NSLOTS 256

__device__ double g_num[NSLOTS];
__device__ double g_den[NSLOTS];

__global__ void zero_acc_kernel() {
    int t = threadIdx.x;
    g_num[t] = 0.0;
    g_den[t] = 0.0;
}

// Grid: (1, 254, 124)  block: 256
//   threadIdx.x = w (0..255, full W row; interior contribution only for 1..254)
//   blockIdx.y  = h-1 (h in 1..254)
//   blockIdx.z  = b*62 + (d-1)   (b in 0..1, d in 1..62)
__global__ __launch_bounds__(256) void vort_kernel(
    const float* __restrict__ pred,
    const float* __restrict__ trgt,
    const float* __restrict__ mask)
{
    constexpr int D = 64, H = 256, W = 256;
    constexpr long sD = (long)H * W;        // 65536
    constexpr long sH = W;                  // 256
    constexpr long CS = (long)D * H * W;    // channel stride 4194304

    const int tid = threadIdx.x;            // = w
    const int h   = blockIdx.y + 1;         // 1..254
    const int zz  = blockIdx.z;
    const int b   = zz / 62;
    const int d   = zz - b * 62 + 1;        // 1..62

    const long mbase = ((long)b * D + d) * sD + (long)h * W + tid;

    // Cooperative near-wall: column-min over the 3x3 (dz,dy) neighborhood at this w.
    // All 9 loads are fully coalesced full-row reads.
    float cmin = 1.0f;
    float mc = 0.0f;
    #pragma unroll
    for (int dz = -1; dz <= 1; dz++) {
        #pragma unroll
        for (int dy = -1; dy <= 1; dy++) {
            float mv = __ldg(mask + mbase + (long)dz * sD + (long)dy * sH);
            if (dz == 0 && dy == 0) mc = mv;
            cmin = fminf(cmin, mv);
        }
    }

    __shared__ float sh_cmin[256];
    sh_cmin[tid] = cmin;
    __syncthreads();

    float numer = 0.0f;
    int   den   = 0;

    if (tid >= 1 && tid <= 254 && mc > 0.5f) {
        // near-wall iff min over full 3^3 neighborhood is 0
        float nmin = fminf(sh_cmin[tid - 1], fminf(cmin, sh_cmin[tid + 1]));
        if (nmin > 0.5f) {
            den = 1;
            // vorticity of (pred - trgt); scale(10) / (2*DELTA=10) cancels exactly.
            const long pb = (long)b * 4 * CS + (long)d * sD + (long)h * W + tid;
            const float* pu = pred + pb + 1 * CS;
            const float* pv = pred + pb + 2 * CS;
            const float* pw = pred + pb + 3 * CS;
            const float* tu = trgt + pb + 1 * CS;
            const float* tv = trgt + pb + 2 * CS;
            const float* tw = trgt + pb + 3 * CS;

            float Du_D = (__ldg(pu + sD) - __ldg(tu + sD)) - (__ldg(pu - sD) - __ldg(tu - sD));
            float Du_H = (__ldg(pu + sH) - __ldg(tu + sH)) - (__ldg(pu - sH) - __ldg(tu - sH));
            float Dv_D = (__ldg(pv + sD) - __ldg(tv + sD)) - (__ldg(pv - sD) - __ldg(tv - sD));
            float Dv_W = (__ldg(pv + 1 ) - __ldg(tv + 1 )) - (__ldg(pv - 1 ) - __ldg(tv - 1 ));
            float Dw_H = (__ldg(pw + sH) - __ldg(tw + sH)) - (__ldg(pw - sH) - __ldg(tw - sH));
            float Dw_W = (__ldg(pw + 1 ) - __ldg(tw + 1 )) - (__ldg(pw - 1 ) - __ldg(tw - 1 ));

            float vx = Dw_H - Dv_D;
            float vy = Du_D - Dw_W;
            float vz = Dv_W - Du_H;
            float sq = vx * vx + vy * vy + vz * vz;
            numer = sqrtf(sq);
        }
    }

    // ---- block reduction (all 256 threads participate; no early returns above) ----
    #pragma unroll
    for (int s = 16; s; s >>= 1) {
        numer += __shfl_down_sync(0xffffffffu, numer, s);
        den   += __shfl_down_sync(0xffffffffu, den,   s);
    }
    __shared__ float wn[8];
    __shared__ int   wd[8];
    const int wid  = tid >> 5;
    const int lane = tid & 31;
    if (lane == 0) { wn[wid] = numer; wd[wid] = den; }
    __syncthreads();
    if (wid == 0) {
        float n2 = (lane < 8) ? wn[lane] : 0.0f;
        int   d2 = (lane < 8) ? wd[lane] : 0;
        #pragma unroll
        for (int s = 4; s; s >>= 1) {
            n2 += __shfl_down_sync(0xffffffffu, n2, s);
            d2 += __shfl_down_sync(0xffffffffu, d2, s);
        }
        if (lane == 0) {
            int slot = (int)((blockIdx.z * gridDim.y + blockIdx.y) & (NSLOTS - 1));
            atomicAdd(&g_num[slot], (double)n2);
            atomicAdd(&g_den[slot], (double)d2);
        }
    }
}

__global__ void finalize_kernel(float* out) {
    __shared__ double sn[NSLOTS];
    __shared__ double sd[NSLOTS];
    int t = threadIdx.x;
    sn[t] = g_num[t];
    sd[t] = g_den[t];
    __syncthreads();
    #pragma unroll
    for (int s = NSLOTS / 2; s; s >>= 1) {
        if (t < s) { sn[t] += sn[t + s]; sd[t] += sd[t + s]; }
        __syncthreads();
    }
    if (t == 0) out[0] = (float)(sn[0] / sd[0]);
}

extern "C" void kernel_launch(void* const* d_in, const int* in_sizes, int n_in,
                              void* d_out, int out_size) {
    const float* pred = (const float*)d_in[0];   // predicts (2,4,64,256,256)
    const float* trgt = (const float*)d_in[1];   // targets  (2,4,64,256,256)
    const float* mask = (const float*)d_in[2];   // masks    (2,1,64,256,256)
    float* out = (float*)d_out;

    zero_acc_kernel<<<1, NSLOTS>>>();
    dim3 grid(1, 254, 124);
    vort_kernel<<<grid, 256>>>(pred, trgt, mask);
    finalize_kernel<<<1, NSLOTS>>>(out);
}